// round 1
// baseline (speedup 1.0000x reference)
#include <cuda_runtime.h>

// Problem constants
#define BB   16      // batch
#define NN   16      // N
#define KK2  8       // K
#define HH   128     // H
#define C2   256     // 2H
#define NI   128     // N*K  (pair index range per side)
#define JT   64      // j-tile per CTA
#define STR  68      // padded smem row stride for h tile (floats)

// Scratch (device globals: allocation-free contract)
__device__ float g_A   [BB * NI * C2];      // A[b][i][c]   = W1[:, :128] @ enc[b,i]
__device__ float g_Bvt [BB * C2 * NI];      // Bvt[b][c][j] = (W1[:,128:] @ enc[b,j])[c]
__device__ float g_part[BB * NI * 2 * C2];  // per-(b,i,jhalf) column partial sums

// ---------------------------------------------------------------------------
// Phase 1: per-vector half-projections of layer 1.
// grid = B*NI (2048), block = 256 (thread = output channel o)
// ---------------------------------------------------------------------------
__global__ void k_ab(const float* __restrict__ enc, const float* __restrict__ W1)
{
    int v   = blockIdx.x;          // v = b*128 + i  (i = n*8 + k)
    int tid = threadIdx.x;         // output channel o in [0,256)

    __shared__ float e[HH];
    if (tid < HH) e[tid] = enc[v * HH + tid];
    __syncthreads();

    const float* w = W1 + tid * C2;
    float a = 0.f, bv = 0.f;
#pragma unroll 8
    for (int h = 0; h < HH; h++) {
        float ev = e[h];
        a  = fmaf(w[h],        ev, a);
        bv = fmaf(w[HH + h],   ev, bv);
    }
    int b = v >> 7, i = v & 127;
    g_A  [v * C2 + tid]            = a;
    g_Bvt[(b * C2 + tid) * NI + i] = bv;
}

// ---------------------------------------------------------------------------
// Phase 2: main fused MLP over pair tiles.
// CTA = (b, i, jhalf): 64 pairs (rows) x full 256 channels.
// h tile kept transposed in smem: h[c*STR + r]. Weights streamed in 32-wide
// K-chunks, transposed in smem: wt[kk*256 + out].
// Each thread: 4 rows x 16 cols micro-tile (64 fp32 accumulators).
// grid = B*NI*2 (4096), block = 256, dyn smem = (256*STR + 32*256)*4 = 100KB
// ---------------------------------------------------------------------------
__global__ __launch_bounds__(256, 2)
void k_main(const float* __restrict__ W2, const float* __restrict__ W3)
{
    extern __shared__ float s[];
    float* h  = s;               // 256 * STR floats (h1^T, later h2^T)
    float* wt = s + C2 * STR;    // 32 * 256 floats (W chunk; reused as reduce scratch)

    int tid = threadIdx.x;
    int tx  = tid & 15;          // col group: cols tx*16 .. tx*16+15
    int ty  = tid >> 4;          // row group: rows ty*4 .. ty*4+3

    int bi  = blockIdx.x;
    int b   = bi >> 8;
    int rem = bi & 255;
    int i   = rem >> 1;
    int jh  = rem & 1;
    int j0  = jh * JT;

    // ---- build h1^T: h[c][r] = relu(A[b,i,c] + Bv[b, j0+r, c]) ----
    {
        float a         = g_A[(b * NI + i) * C2 + tid];          // c = tid
        const float* bp = g_Bvt + (b * C2 + tid) * NI + j0;
        float* hr       = h + tid * STR;
#pragma unroll
        for (int m = 0; m < JT / 4; m++) {
            float4 v = *(const float4*)(bp + 4 * m);
            v.x = fmaxf(v.x + a, 0.f);
            v.y = fmaxf(v.y + a, 0.f);
            v.z = fmaxf(v.z + a, 0.f);
            v.w = fmaxf(v.w + a, 0.f);
            *(float4*)(hr + 4 * m) = v;
        }
    }

    for (int layer = 0; layer < 2; layer++) {
        const float* Wg = layer ? W3 : W2;

        float acc[4][16];
#pragma unroll
        for (int r = 0; r < 4; r++)
#pragma unroll
            for (int c = 0; c < 16; c++) acc[r][c] = 0.f;

        for (int kt = 0; kt < C2; kt += 32) {
            __syncthreads();   // h writes visible (first iter) / wt reads done (later)
            // stage W chunk transposed: thread = out channel, 32 contiguous k's
            {
                const float* wrow = Wg + tid * C2 + kt;
#pragma unroll
                for (int m = 0; m < 8; m++) {
                    float4 w4 = *(const float4*)(wrow + 4 * m);
                    wt[(4 * m + 0) * C2 + tid] = w4.x;
                    wt[(4 * m + 1) * C2 + tid] = w4.y;
                    wt[(4 * m + 2) * C2 + tid] = w4.z;
                    wt[(4 * m + 3) * C2 + tid] = w4.w;
                }
            }
            __syncthreads();

#pragma unroll 4
            for (int kk = 0; kk < 32; kk++) {
                float4 a4 = *(const float4*)(h + (kt + kk) * STR + ty * 4);
                float av[4] = {a4.x, a4.y, a4.z, a4.w};
#pragma unroll
                for (int g = 0; g < 4; g++) {
                    float4 w4 = *(const float4*)(wt + kk * C2 + tx * 16 + 4 * g);
                    float wv[4] = {w4.x, w4.y, w4.z, w4.w};
#pragma unroll
                    for (int r = 0; r < 4; r++) {
#pragma unroll
                        for (int q = 0; q < 4; q++)
                            acc[r][4 * g + q] = fmaf(av[r], wv[q], acc[r][4 * g + q]);
                    }
                }
            }
        }
        __syncthreads();   // all h reads done before overwrite / scratch reuse

        if (layer == 0) {
            // relu + write h2^T back over h
#pragma unroll
            for (int r = 0; r < 4; r++)
#pragma unroll
                for (int c = 0; c < 16; c++)
                    h[(tx * 16 + c) * STR + (ty * 4 + r)] = fmaxf(acc[r][c], 0.f);
            // next layer's first top-of-loop __syncthreads makes these visible
        } else {
            // relu + deterministic reduce over the CTA's 64 rows
#pragma unroll
            for (int c = 0; c < 16; c++) {
                float sv = fmaxf(acc[0][c], 0.f) + fmaxf(acc[1][c], 0.f)
                         + fmaxf(acc[2][c], 0.f) + fmaxf(acc[3][c], 0.f);
                wt[ty * C2 + tx * 16 + c] = sv;   // wt reused as [16][256] scratch
            }
            __syncthreads();
            float sum = 0.f;
#pragma unroll
            for (int t = 0; t < 16; t++) sum += wt[t * C2 + tid];
            g_part[((b * NI + i) * 2 + jh) * C2 + tid] = sum;
        }
    }
}

// ---------------------------------------------------------------------------
// Phase 3: out[b][n1][c] = mean over (k1, jhalf) partials / 1024
// ---------------------------------------------------------------------------
__global__ void k_fin(float* __restrict__ out)
{
    int idx = blockIdx.x * 256 + threadIdx.x;  // (b*16 + n1)*256 + c
    int c   = idx & 255;
    int bn  = idx >> 8;
    int b   = bn >> 4;
    int n1  = bn & 15;

    float sum = 0.f;
#pragma unroll
    for (int k1 = 0; k1 < 8; k1++)
#pragma unroll
        for (int jh = 0; jh < 2; jh++)
            sum += g_part[((b * NI + n1 * 8 + k1) * 2 + jh) * C2 + c];

    out[idx] = sum * (1.0f / 1024.0f);
}

// ---------------------------------------------------------------------------
extern "C" void kernel_launch(void* const* d_in, const int* in_sizes, int n_in,
                              void* d_out, int out_size)
{
    const float* enc = (const float*)d_in[0];
    const float* W1  = (const float*)d_in[1];
    const float* W2  = (const float*)d_in[2];
    const float* W3  = (const float*)d_in[3];
    float* out       = (float*)d_out;

    const int smem_bytes = (C2 * STR + 32 * C2) * (int)sizeof(float);  // 102400
    cudaFuncSetAttribute(k_main, cudaFuncAttributeMaxDynamicSharedMemorySize, smem_bytes);

    k_ab  <<<BB * NI, 256>>>(enc, W1);
    k_main<<<BB * NI * 2, 256, smem_bytes>>>(W2, W3);
    k_fin <<<(BB * NN * C2) / 256, 256>>>(out);
}

// round 2
// speedup vs baseline: 4.7671x; 4.7671x over previous
#include <cuda_runtime.h>

// Problem constants
#define BB   16
#define NN   16
#define HH   128
#define C2   256     // 2H
#define NI   128     // N*K
#define JT   64      // rows (j) per CTA in k_main
#define HSTR 260     // h tile row stride (floats): bank=(4r+c)%32 conflict-free
#define WSTR 37      // W chunk row stride (floats): 5*tid odd-stride, conflict-free stores
#define WCHUNK 32

// Scratch (device globals: allocation-free contract)
__device__ float g_A   [BB * NI * C2];      // A[b][i][c]   = W1[:, :128] @ enc[b,i]
__device__ float g_Bvt [BB * C2 * NI];      // Bvt[b][c][j] = (W1[:,128:] @ enc[b,j])[c]
__device__ float g_part[BB * NI * 2 * C2];  // per-(b,i,jhalf) column partial sums

__device__ __forceinline__ float f2tf(float f) {
    unsigned u;
    asm("cvt.rna.tf32.f32 %0, %1;" : "=r"(u) : "f"(f));
    return __uint_as_float(u);
}

__device__ __forceinline__ void mma8(float* c, const unsigned* a, const unsigned* b) {
    asm volatile(
        "mma.sync.aligned.m16n8k8.row.col.f32.tf32.tf32.f32 "
        "{%0,%1,%2,%3}, {%4,%5,%6,%7}, {%8,%9}, {%0,%1,%2,%3};"
        : "+f"(c[0]), "+f"(c[1]), "+f"(c[2]), "+f"(c[3])
        : "r"(a[0]), "r"(a[1]), "r"(a[2]), "r"(a[3]), "r"(b[0]), "r"(b[1]));
}

// ---------------------------------------------------------------------------
// Phase 1: layer-1 half projections. 128 blocks x 256 threads, 16 vectors/blk.
// Coalesced W1 staging through smem (the round-1 version was 455us of
// uncoalesced scalar LDG latency).
// ---------------------------------------------------------------------------
__global__ __launch_bounds__(256) void k_ab(const float* __restrict__ enc,
                                            const float* __restrict__ W1)
{
    __shared__ float e_s[16 * HH];      // 8 KB
    __shared__ float w_s[C2 * 33];      // 33.8 KB, stride 33: (tid+k)%32 banks
    int tid = threadIdx.x;
    int vb  = blockIdx.x * 16;          // 16 vectors per block, same b (128%16==0)

    for (int idx = tid; idx < 16 * HH / 4; idx += 256)
        ((float4*)e_s)[idx] = ((const float4*)(enc + vb * HH))[idx];

    float acc[2][16];
#pragma unroll
    for (int hf = 0; hf < 2; hf++)
#pragma unroll
        for (int v = 0; v < 16; v++) acc[hf][v] = 0.f;

    for (int kt = 0; kt < C2; kt += 32) {
        __syncthreads();
        // coalesced stage of W1[:, kt:kt+32]
#pragma unroll 8
        for (int rep = 0; rep < 32; rep++) {
            int o = rep * 8 + (tid >> 5);
            int c = tid & 31;
            w_s[o * 33 + c] = W1[o * C2 + kt + c];
        }
        __syncthreads();

        int hf = kt >> 7;        // 0: A-half (k<128), 1: B-half
        int kb = kt & 127;
#pragma unroll 8
        for (int kk = 0; kk < 32; kk++) {
            float wv = w_s[tid * 33 + kk];
#pragma unroll
            for (int v = 0; v < 16; v++)
                acc[hf][v] = fmaf(wv, e_s[v * HH + kb + kk], acc[hf][v]);
        }
    }

    int b = vb >> 7, i0 = vb & 127;
#pragma unroll
    for (int v = 0; v < 16; v++) {
        g_A  [(vb + v) * C2 + tid]           = acc[0][v];
        g_Bvt[(b * C2 + tid) * NI + i0 + v]  = acc[1][v];
    }
}

// ---------------------------------------------------------------------------
// Phase 2: fused 2-layer GEMM on tensor cores (tf32 mma.sync m16n8k8).
// CTA = (b, i, jhalf): 64 pair-rows x 256 out channels, K=256, twice.
// 8 warps: wy in {0,1} (32 rows each), wx in {0..3} (64 cols each).
// Warp tile 32x64 = 2 m-tiles x 8 n-tiles. 64 fp32 accums/thread.
// dyn smem = (64*260 + 256*37)*4 = 104448 B -> 2 CTAs/SM.
// ---------------------------------------------------------------------------
__global__ __launch_bounds__(256, 2) void k_main(const float* __restrict__ W2,
                                                 const float* __restrict__ W3)
{
    extern __shared__ float s[];
    float* h  = s;               // JT * HSTR (h1, then h2), tf32-rounded fp32
    float* ws = s + JT * HSTR;   // C2 * WSTR W chunk; reused as reduce scratch

    int tid  = threadIdx.x;
    int lane = tid & 31;
    int wid  = tid >> 5;
    int wy   = wid & 1;          // m group
    int wx   = wid >> 1;         // n group
    int mrow = wy * 32;
    int ncol = wx * 64;

    int bi  = blockIdx.x;
    int b   = bi >> 8;
    int rem = bi & 255;
    int i   = rem >> 1;
    int jh  = rem & 1;
    int j0  = jh * JT;

    // ---- build h1[r][c] = relu(A[b,i,c] + Bv[b, j0+r, c]), tf32-rounded ----
    {
        float a         = g_A[(b * NI + i) * C2 + tid];     // c = tid
        const float* bp = g_Bvt + (b * C2 + tid) * NI + j0;
#pragma unroll
        for (int r4 = 0; r4 < JT; r4 += 4) {
            float4 v = *(const float4*)(bp + r4);
            h[(r4 + 0) * HSTR + tid] = f2tf(fmaxf(v.x + a, 0.f));
            h[(r4 + 1) * HSTR + tid] = f2tf(fmaxf(v.y + a, 0.f));
            h[(r4 + 2) * HSTR + tid] = f2tf(fmaxf(v.z + a, 0.f));
            h[(r4 + 3) * HSTR + tid] = f2tf(fmaxf(v.w + a, 0.f));
        }
    }

    for (int layer = 0; layer < 2; layer++) {
        const float* Wg = layer ? W3 : W2;

        float acc[2][8][4];
#pragma unroll
        for (int mt = 0; mt < 2; mt++)
#pragma unroll
            for (int t = 0; t < 8; t++)
#pragma unroll
                for (int q = 0; q < 4; q++) acc[mt][t][q] = 0.f;

        for (int kt = 0; kt < C2; kt += WCHUNK) {
            __syncthreads();   // h/ws writes visible; prior ws reads done
            {   // stage W chunk: row o=tid, cols kt..kt+31, tf32-rounded
                const float* wr = Wg + tid * C2 + kt;
                float* wd       = ws + tid * WSTR;
#pragma unroll
                for (int m = 0; m < 8; m++) {
                    float4 w4 = *(const float4*)(wr + 4 * m);
                    wd[4 * m + 0] = f2tf(w4.x);
                    wd[4 * m + 1] = f2tf(w4.y);
                    wd[4 * m + 2] = f2tf(w4.z);
                    wd[4 * m + 3] = f2tf(w4.w);
                }
            }
            __syncthreads();

#pragma unroll
            for (int ks = 0; ks < 4; ks++) {
                int k  = kt + ks * 8;
                int ar = mrow + (lane >> 2);
                int ac = k + (lane & 3);
                unsigned a[2][4];
#pragma unroll
                for (int mt = 0; mt < 2; mt++) {
                    const float* hp = h + (ar + mt * 16) * HSTR + ac;
                    a[mt][0] = __float_as_uint(hp[0]);
                    a[mt][1] = __float_as_uint(hp[8 * HSTR]);
                    a[mt][2] = __float_as_uint(hp[4]);
                    a[mt][3] = __float_as_uint(hp[8 * HSTR + 4]);
                }
#pragma unroll
                for (int t = 0; t < 8; t++) {
                    unsigned bf[2];
                    const float* wp = ws + (ncol + t * 8 + (lane >> 2)) * WSTR
                                         + ks * 8 + (lane & 3);
                    bf[0] = __float_as_uint(wp[0]);
                    bf[1] = __float_as_uint(wp[4]);
                    mma8(acc[0][t], a[0], bf);
                    mma8(acc[1][t], a[1], bf);
                }
            }
        }
        __syncthreads();   // all h/ws reads done before overwrite

        if (layer == 0) {
            // relu + tf32 + write h2 back over h
#pragma unroll
            for (int mt = 0; mt < 2; mt++) {
                int r = mrow + mt * 16 + (lane >> 2);
#pragma unroll
                for (int t = 0; t < 8; t++) {
                    int c = ncol + t * 8 + 2 * (lane & 3);
                    h[r * HSTR + c]           = f2tf(fmaxf(acc[mt][t][0], 0.f));
                    h[r * HSTR + c + 1]       = f2tf(fmaxf(acc[mt][t][1], 0.f));
                    h[(r + 8) * HSTR + c]     = f2tf(fmaxf(acc[mt][t][2], 0.f));
                    h[(r + 8) * HSTR + c + 1] = f2tf(fmaxf(acc[mt][t][3], 0.f));
                }
            }
        } else {
            // relu + deterministic row-sum over the CTA's 64 rows
            float* red = ws;   // reuse as [2][256] scratch
#pragma unroll
            for (int t = 0; t < 8; t++) {
                float ev = fmaxf(acc[0][t][0], 0.f) + fmaxf(acc[0][t][2], 0.f)
                         + fmaxf(acc[1][t][0], 0.f) + fmaxf(acc[1][t][2], 0.f);
                float od = fmaxf(acc[0][t][1], 0.f) + fmaxf(acc[0][t][3], 0.f)
                         + fmaxf(acc[1][t][1], 0.f) + fmaxf(acc[1][t][3], 0.f);
#pragma unroll
                for (int o = 4; o <= 16; o <<= 1) {
                    ev += __shfl_xor_sync(0xffffffffu, ev, o);
                    od += __shfl_xor_sync(0xffffffffu, od, o);
                }
                if (lane < 4) {
                    red[wy * C2 + ncol + t * 8 + 2 * lane]     = ev;
                    red[wy * C2 + ncol + t * 8 + 2 * lane + 1] = od;
                }
            }
            __syncthreads();
            float sum = red[tid] + red[C2 + tid];
            g_part[((b * NI + i) * 2 + jh) * C2 + tid] = sum;
        }
    }
}

// ---------------------------------------------------------------------------
// Phase 3: out[b][n1][c] = mean over (k1, jhalf) partials / 1024
// ---------------------------------------------------------------------------
__global__ void k_fin(float* __restrict__ out)
{
    int idx = blockIdx.x * 256 + threadIdx.x;
    int c   = idx & 255;
    int bn  = idx >> 8;
    int b   = bn >> 4;
    int n1  = bn & 15;

    float sum = 0.f;
#pragma unroll
    for (int k1 = 0; k1 < 8; k1++)
#pragma unroll
        for (int jhv = 0; jhv < 2; jhv++)
            sum += g_part[((b * NI + n1 * 8 + k1) * 2 + jhv) * C2 + c];

    out[idx] = sum * (1.0f / 1024.0f);
}

// ---------------------------------------------------------------------------
extern "C" void kernel_launch(void* const* d_in, const int* in_sizes, int n_in,
                              void* d_out, int out_size)
{
    const float* enc = (const float*)d_in[0];
    const float* W1  = (const float*)d_in[1];
    const float* W2  = (const float*)d_in[2];
    const float* W3  = (const float*)d_in[3];
    float* out       = (float*)d_out;

    const int smem_bytes = (JT * HSTR + C2 * WSTR) * (int)sizeof(float);  // 104448
    cudaFuncSetAttribute(k_main, cudaFuncAttributeMaxDynamicSharedMemorySize, smem_bytes);

    k_ab  <<<BB * NI / 16, 256>>>(enc, W1);
    k_main<<<BB * NI * 2, 256, smem_bytes>>>(W2, W3);
    k_fin <<<(BB * NN * C2) / 256, 256>>>(out);
}

// round 3
// speedup vs baseline: 8.3450x; 1.7505x over previous
#include <cuda_runtime.h>
#include <cstdint>

// Problem constants
#define BB   16
#define NN   16
#define HH   128
#define C2   256     // 2H
#define NI   128     // N*K
#define JT   128     // j rows per CTA (all of them)
#define HSTR 264     // h tile row stride (words); 264 % 32 == 8 -> LDS.64 conflict-free
#define WSTR 36      // W chunk row stride (words); 36*(lane>>2)+(lane&3) distinct mod 32
#define NCH  16      // 8 K-chunks x 2 layers

// Scratch (device globals: allocation-free contract)
__device__ float g_A   [BB * NI * C2];
__device__ float g_Bvt [BB * C2 * NI];
__device__ float g_part[BB * NI * C2];

__device__ __forceinline__ float f2tf(float f) {
    unsigned u;
    asm("cvt.rna.tf32.f32 %0, %1;" : "=r"(u) : "f"(f));
    return __uint_as_float(u);
}

__device__ __forceinline__ void mma8(float* c, const unsigned* a, const unsigned* b) {
    asm volatile(
        "mma.sync.aligned.m16n8k8.row.col.f32.tf32.tf32.f32 "
        "{%0,%1,%2,%3}, {%4,%5,%6,%7}, {%8,%9}, {%0,%1,%2,%3};"
        : "+f"(c[0]), "+f"(c[1]), "+f"(c[2]), "+f"(c[3])
        : "r"(a[0]), "r"(a[1]), "r"(a[2]), "r"(a[3]), "r"(b[0]), "r"(b[1]));
}

__device__ __forceinline__ uint32_t smem_u32(const void* p) {
    return (uint32_t)__cvta_generic_to_shared(p);
}
__device__ __forceinline__ void cpa16(uint32_t dst, const float* src) {
    asm volatile("cp.async.cg.shared.global [%0], [%1], 16;" :: "r"(dst), "l"(src));
}
__device__ __forceinline__ void cpa_commit() { asm volatile("cp.async.commit_group;"); }
__device__ __forceinline__ void cpa_wait0()  { asm volatile("cp.async.wait_group 0;"); }

// column permutation within each 8-col k-group: k -> (k&~7) | ((k&3)<<1) | ((k>>2)&1)
// puts (c, c+4) adjacent so A fragments load as LDS.64
__device__ __forceinline__ int pg(int c) {
    return (c & ~7) | ((c & 3) << 1) | ((c >> 2) & 1);
}

// ---------------------------------------------------------------------------
// Phase 1: layer-1 half projections. 512 blocks x 4 vectors (4x parallelism
// vs round 2; float4 weight loads).
// ---------------------------------------------------------------------------
__global__ __launch_bounds__(256) void k_ab(const float* __restrict__ enc,
                                            const float* __restrict__ W1)
{
    __shared__ float e_s[4 * HH];
    __shared__ float w_s[C2 * 33];      // stride 33 -> conflict-free row reads
    int tid = threadIdx.x;
    int vb  = blockIdx.x * 4;

    if (tid < 128) ((float4*)e_s)[tid] = ((const float4*)(enc + vb * HH))[tid];

    float acc[2][4];
#pragma unroll
    for (int hf = 0; hf < 2; hf++)
#pragma unroll
        for (int v = 0; v < 4; v++) acc[hf][v] = 0.f;

    for (int kt = 0; kt < C2; kt += 32) {
        __syncthreads();
#pragma unroll
        for (int r = 0; r < 8; r++) {           // 2048 float4 / 256 threads
            int idx = tid + r * 256;
            int o   = idx >> 3;
            int c4  = idx & 7;
            float4 w4 = *(const float4*)(W1 + o * C2 + kt + c4 * 4);
            w_s[o * 33 + c4 * 4 + 0] = w4.x;
            w_s[o * 33 + c4 * 4 + 1] = w4.y;
            w_s[o * 33 + c4 * 4 + 2] = w4.z;
            w_s[o * 33 + c4 * 4 + 3] = w4.w;
        }
        __syncthreads();

        int hf = kt >> 7;
        int kb = kt & 127;
#pragma unroll 8
        for (int kk = 0; kk < 32; kk++) {
            float wv = w_s[tid * 33 + kk];
#pragma unroll
            for (int v = 0; v < 4; v++)
                acc[hf][v] = fmaf(wv, e_s[v * HH + kb + kk], acc[hf][v]);
        }
    }

    int b = vb >> 7, i0 = vb & 127;
#pragma unroll
    for (int v = 0; v < 4; v++) {
        g_A  [(vb + v) * C2 + tid]          = acc[0][v];
        g_Bvt[(b * C2 + tid) * NI + i0 + v] = acc[1][v];
    }
}

// ---------------------------------------------------------------------------
// Phase 2: fused 2-layer GEMM, cp.async double-buffered weights.
// CTA = (b, i): 128 pair-rows x 256 cols, K=256, two layers.
// 512 threads, 16 warps (2 wy x 8 wx), warp tile 64x32 (4 m-tiles x 4 n-tiles).
// smem: h[128][264] + 2 weight buffers [256][36]  = 208896 B -> 1 CTA/SM.
// ---------------------------------------------------------------------------
__global__ __launch_bounds__(512, 1) void k_main(const float* __restrict__ W2,
                                                 const float* __restrict__ W3)
{
    extern __shared__ float s[];
    float* h  = s;                        // 128 * 264
    float* ws = s + JT * HSTR;            // 2 * 256 * 36
    uint32_t ws_u32 = smem_u32(ws);

    int tid  = threadIdx.x;
    int lane = tid & 31;
    int wid  = tid >> 5;
    int wy   = wid & 1;                   // 64-row group
    int wx   = wid >> 1;                  // 32-col group
    int mrow = wy * 64;
    int ncol = wx * 32;

    int bi = blockIdx.x;
    int b  = bi >> 7;
    int i  = bi & 127;

    // ---- prefetch chunk 0 (W2 cols 0..31) ----
    {
#pragma unroll
        for (int r = 0; r < 4; r++) {     // 2048 float4 / 512 threads
            int idx = tid + r * 512;
            int o   = idx >> 3;
            int c4  = idx & 7;
            cpa16(ws_u32 + (uint32_t)(o * WSTR + c4 * 4) * 4,
                  W2 + o * C2 + c4 * 4);
        }
        cpa_commit();
    }

    // ---- build h1 (permuted columns, tf32-rounded) while chunk 0 flies ----
    {
        int c    = tid & 255;
        int row0 = (tid >> 8) * 64;
        float a  = g_A[(b * NI + i) * C2 + c];
        const float* bp = g_Bvt + (b * C2 + c) * NI + row0;
        int pc = pg(c);
#pragma unroll
        for (int r4 = 0; r4 < 64; r4 += 4) {
            float4 v = *(const float4*)(bp + r4);
            h[(row0 + r4 + 0) * HSTR + pc] = f2tf(fmaxf(v.x + a, 0.f));
            h[(row0 + r4 + 1) * HSTR + pc] = f2tf(fmaxf(v.y + a, 0.f));
            h[(row0 + r4 + 2) * HSTR + pc] = f2tf(fmaxf(v.z + a, 0.f));
            h[(row0 + r4 + 3) * HSTR + pc] = f2tf(fmaxf(v.w + a, 0.f));
        }
    }

    float acc[4][4][4];
#pragma unroll
    for (int mt = 0; mt < 4; mt++)
#pragma unroll
        for (int t = 0; t < 4; t++)
#pragma unroll
            for (int q = 0; q < 4; q++) acc[mt][t][q] = 0.f;

    for (int ck = 0; ck < NCH; ck++) {
        cpa_wait0();            // chunk ck landed (issued one compute-phase ago)
        __syncthreads();        // visible to all; prev buffer free for reuse

        if (ck < NCH - 1) {     // prefetch chunk ck+1 into the other buffer
            int nc = ck + 1;
            const float* Wg = (nc < 8) ? W2 : W3;
            int kt = (nc & 7) * 32;
            uint32_t dbase = ws_u32 + (uint32_t)((nc & 1) * C2 * WSTR) * 4;
#pragma unroll
            for (int r = 0; r < 4; r++) {
                int idx = tid + r * 512;
                int o   = idx >> 3;
                int c4  = idx & 7;
                cpa16(dbase + (uint32_t)(o * WSTR + c4 * 4) * 4,
                      Wg + o * C2 + kt + c4 * 4);
            }
            cpa_commit();
        }

        // ---- compute chunk ck ----
        float* wb = ws + (ck & 1) * C2 * WSTR;
        int hk = (ck & 7) * 32;
#pragma unroll
        for (int ks = 0; ks < 4; ks++) {
            unsigned a[4][4];
#pragma unroll
            for (int mt = 0; mt < 4; mt++) {
                const float* ap = h + (mrow + mt * 16 + (lane >> 2)) * HSTR
                                    + hk + ks * 8 + 2 * (lane & 3);
                uint2 lo = *(const uint2*)ap;               // (c, c+4) row r
                uint2 hi = *(const uint2*)(ap + 8 * HSTR);  // row r+8
                a[mt][0] = lo.x; a[mt][2] = lo.y;
                a[mt][1] = hi.x; a[mt][3] = hi.y;
            }
#pragma unroll
            for (int t = 0; t < 4; t++) {
                const float* wp = wb + (ncol + t * 8 + (lane >> 2)) * WSTR
                                     + ks * 8 + (lane & 3);
                unsigned bf[2];
                bf[0] = __float_as_uint(wp[0]);
                bf[1] = __float_as_uint(wp[4]);
#pragma unroll
                for (int mt = 0; mt < 4; mt++) mma8(acc[mt][t], a[mt], bf);
            }
        }

        if (ck == 7) {
            // layer boundary: all warps done with h1, write h2 (permuted)
            __syncthreads();
#pragma unroll
            for (int mt = 0; mt < 4; mt++) {
                int r = mrow + mt * 16 + (lane >> 2);
#pragma unroll
                for (int t = 0; t < 4; t++) {
                    int c0 = ncol + t * 8 + 2 * (lane & 3);
                    h[r * HSTR + pg(c0)]           = f2tf(fmaxf(acc[mt][t][0], 0.f));
                    h[r * HSTR + pg(c0 + 1)]       = f2tf(fmaxf(acc[mt][t][1], 0.f));
                    h[(r + 8) * HSTR + pg(c0)]     = f2tf(fmaxf(acc[mt][t][2], 0.f));
                    h[(r + 8) * HSTR + pg(c0 + 1)] = f2tf(fmaxf(acc[mt][t][3], 0.f));
#pragma unroll
                    for (int q = 0; q < 4; q++) acc[mt][t][q] = 0.f;
                }
            }
            // next iteration's __syncthreads orders these writes before reads
        }
    }

    // ---- final: relu + deterministic sum over all 128 rows ----
    __syncthreads();            // weight-buffer reads done; reuse ws as scratch
    float* red = ws;            // [2][256]
#pragma unroll
    for (int t = 0; t < 4; t++) {
        float ev = 0.f, od = 0.f;
#pragma unroll
        for (int mt = 0; mt < 4; mt++) {
            ev += fmaxf(acc[mt][t][0], 0.f) + fmaxf(acc[mt][t][2], 0.f);
            od += fmaxf(acc[mt][t][1], 0.f) + fmaxf(acc[mt][t][3], 0.f);
        }
#pragma unroll
        for (int o = 4; o <= 16; o <<= 1) {
            ev += __shfl_xor_sync(0xffffffffu, ev, o);
            od += __shfl_xor_sync(0xffffffffu, od, o);
        }
        if (lane < 4) {
            red[wy * C2 + ncol + t * 8 + 2 * lane]     = ev;
            red[wy * C2 + ncol + t * 8 + 2 * lane + 1] = od;
        }
    }
    __syncthreads();
    if (tid < C2)
        g_part[(b * NI + i) * C2 + tid] = red[tid] + red[C2 + tid];
}

// ---------------------------------------------------------------------------
// Phase 3: out[b][n1][c] = (1/1024) * sum_{k1<8} part[b][n1*8+k1][c]
// ---------------------------------------------------------------------------
__global__ void k_fin(float* __restrict__ out)
{
    int idx = blockIdx.x * 256 + threadIdx.x;
    int c   = idx & 255;
    int bn  = idx >> 8;
    int b   = bn >> 4;
    int n1  = bn & 15;

    float sum = 0.f;
#pragma unroll
    for (int k1 = 0; k1 < 8; k1++)
        sum += g_part[(b * NI + n1 * 8 + k1) * C2 + c];

    out[idx] = sum * (1.0f / 1024.0f);
}

// ---------------------------------------------------------------------------
extern "C" void kernel_launch(void* const* d_in, const int* in_sizes, int n_in,
                              void* d_out, int out_size)
{
    const float* enc = (const float*)d_in[0];
    const float* W1  = (const float*)d_in[1];
    const float* W2  = (const float*)d_in[2];
    const float* W3  = (const float*)d_in[3];
    float* out       = (float*)d_out;

    const int smem_bytes = (JT * HSTR + 2 * C2 * WSTR) * (int)sizeof(float); // 208896
    cudaFuncSetAttribute(k_main, cudaFuncAttributeMaxDynamicSharedMemorySize, smem_bytes);

    k_ab  <<<BB * NI / 4, 256>>>(enc, W1);
    k_main<<<BB * NI, 512, smem_bytes>>>(W2, W3);
    k_fin <<<(BB * NN * C2) / 256, 256>>>(out);
}

// round 5
// speedup vs baseline: 14.9193x; 1.7878x over previous
#include <cuda_runtime.h>
#include <cuda_fp16.h>
#include <cstdint>

// Problem constants
#define BB 16
#define NN 16
#define HH 128
#define C2 256
#define NI 128

#define HSTR2 272            // h row stride in halves (544 B: conflict-free LDS.64)
#define WS2   48             // weight row stride in halves (96 B: conflict-free, 16B-aligned)
#define WBYTES (256 * WS2 * 2)   // 24576 B per weight buffer
#define NCH 16               // 8 K-chunks x 2 layers

// Scratch (device globals: allocation-free contract)
__device__ float g_A   [BB * NI * C2];
__device__ float g_Bvt [BB * C2 * NI];
__device__ float g_part[BB * NI * C2];
__device__ __align__(16) __half g_Wh[NCH * 256 * 32];  // fp16, k-permuted, chunk-major

__device__ __forceinline__ uint32_t smem_u32(const void* p) {
    return (uint32_t)__cvta_generic_to_shared(p);
}
__device__ __forceinline__ void cpa16(uint32_t dst, const void* src) {
    asm volatile("cp.async.cg.shared.global [%0], [%1], 16;" :: "r"(dst), "l"(src));
}
__device__ __forceinline__ void cpa_commit() { asm volatile("cp.async.commit_group;"); }
__device__ __forceinline__ void cpa_wait0()  { asm volatile("cp.async.wait_group 0;"); }

// fp16 MMA, fp32 accumulate (same 10-bit mantissa as tf32)
__device__ __forceinline__ void mma16(float* c, const uint32_t* a, const uint32_t* b) {
    asm volatile(
        "mma.sync.aligned.m16n8k16.row.col.f32.f16.f16.f32 "
        "{%0,%1,%2,%3}, {%4,%5,%6,%7}, {%8,%9}, {%0,%1,%2,%3};"
        : "+f"(c[0]), "+f"(c[1]), "+f"(c[2]), "+f"(c[3])
        : "r"(a[0]), "r"(a[1]), "r"(a[2]), "r"(a[3]), "r"(b[0]), "r"(b[1]));
}

// k-permutation within each 16-group: logical k -> phys so that
// (2t, 2t+1, 2t+8, 2t+9) land contiguous -> A/B fragments load as LDS.64
__device__ __forceinline__ int pg16(int c) {
    return (c & ~15) | ((c & 6) << 1) | ((c & 8) >> 2) | (c & 1);
}

// ---------------------------------------------------------------------------
// k_round: W2|W3 -> fp16 (rn), chunk-major [16][256][32] with k-permutation
// ---------------------------------------------------------------------------
__global__ void k_round(const float* __restrict__ W2, const float* __restrict__ W3)
{
    int idx = blockIdx.x * 256 + threadIdx.x;   // 131072
    int L = idx >> 16, rem = idx & 65535;
    int o = rem >> 8, k = rem & 255;
    float v = (L ? W3 : W2)[o * C2 + k];
    int ck = (L << 3) | (k >> 5);
    int k5 = k & 31;
    int pr = (k5 & 16) | ((k5 & 6) << 1) | ((k5 & 8) >> 2) | (k5 & 1);
    g_Wh[ck * 8192 + o * 32 + pr] = __float2half_rn(v);
}

// ---------------------------------------------------------------------------
// k_ab: layer-1 half projections (8 vectors/block)
// ---------------------------------------------------------------------------
__global__ __launch_bounds__(256) void k_ab(const float* __restrict__ enc,
                                            const float* __restrict__ W1)
{
    __shared__ float e_s[8 * HH];
    __shared__ float w_s[C2 * 33];
    int tid = threadIdx.x;
    int vb  = blockIdx.x * 8;

    ((float4*)e_s)[tid] = ((const float4*)(enc + vb * HH))[tid];

    float acc[2][8];
#pragma unroll
    for (int hf = 0; hf < 2; hf++)
#pragma unroll
        for (int v = 0; v < 8; v++) acc[hf][v] = 0.f;

    for (int kt = 0; kt < C2; kt += 32) {
        __syncthreads();
#pragma unroll
        for (int r = 0; r < 8; r++) {
            int idx = tid + r * 256;
            int o = idx >> 3, c4 = idx & 7;
            float4 w4 = *(const float4*)(W1 + o * C2 + kt + c4 * 4);
            w_s[o * 33 + c4 * 4 + 0] = w4.x;
            w_s[o * 33 + c4 * 4 + 1] = w4.y;
            w_s[o * 33 + c4 * 4 + 2] = w4.z;
            w_s[o * 33 + c4 * 4 + 3] = w4.w;
        }
        __syncthreads();
        int hf = kt >> 7, kb = kt & 127;
#pragma unroll 8
        for (int kk = 0; kk < 32; kk++) {
            float wv = w_s[tid * 33 + kk];
#pragma unroll
            for (int v = 0; v < 8; v++)
                acc[hf][v] = fmaf(wv, e_s[v * HH + kb + kk], acc[hf][v]);
        }
    }
    int b = vb >> 7, i0 = vb & 127;
#pragma unroll
    for (int v = 0; v < 8; v++) {
        g_A  [(vb + v) * C2 + tid]          = acc[0][v];
        g_Bvt[(b * C2 + tid) * NI + i0 + v] = acc[1][v];
    }
}

// ---------------------------------------------------------------------------
// k_main: fused 2-layer GEMM, fp16 mma.sync.m16n8k16, cp.async double buffer.
// CTA = (b,i): 128 rows x 256 cols, K=256, two layers.
// 512 threads, 16 warps (wy in {0,1} x wx in {0..7}), warp tile 64x32.
// smem: h[128][272] halves (69632 B) + 2 W bufs [256][48] halves (49152 B).
// All fragment LDS.64 loads bank-conflict-free by construction.
// ---------------------------------------------------------------------------
__global__ __launch_bounds__(512, 1) void k_main()
{
    extern __shared__ char smem[];
    __half* h  = (__half*)smem;                         // 128 * 272
    __half* wb = (__half*)(smem + 128 * HSTR2 * 2);     // 2 x [256][48]
    uint32_t wb_u32 = smem_u32(wb);

    int tid  = threadIdx.x;
    int lane = tid & 31;
    int wid  = tid >> 5;
    int wy   = wid & 1;
    int wx   = wid >> 1;
    int mrow = wy * 64;
    int ncol = wx * 32;

    int b = blockIdx.x >> 7;
    int i = blockIdx.x & 127;

    // ---- prefetch chunk 0 ----
#pragma unroll
    for (int r = 0; r < 2; r++) {          // 1024 x 16B / 512 threads
        int idx = tid + r * 512;
        int o = idx >> 2, c4 = idx & 3;
        cpa16(wb_u32 + (uint32_t)(o * 96 + c4 * 16), g_Wh + o * 32 + c4 * 8);
    }
    cpa_commit();

    // ---- build h1 (k-permuted cols, fp16) while chunk 0 flies ----
    {
        int c    = tid & 255;
        int row0 = (tid >> 8) * 64;
        float a  = g_A[(b * NI + i) * C2 + c];
        const float* bp = g_Bvt + (b * C2 + c) * NI + row0;
        int pc = pg16(c);
#pragma unroll
        for (int r4 = 0; r4 < 64; r4 += 4) {
            float4 v = *(const float4*)(bp + r4);
            h[(row0 + r4 + 0) * HSTR2 + pc] = __float2half_rn(fmaxf(v.x + a, 0.f));
            h[(row0 + r4 + 1) * HSTR2 + pc] = __float2half_rn(fmaxf(v.y + a, 0.f));
            h[(row0 + r4 + 2) * HSTR2 + pc] = __float2half_rn(fmaxf(v.z + a, 0.f));
            h[(row0 + r4 + 3) * HSTR2 + pc] = __float2half_rn(fmaxf(v.w + a, 0.f));
        }
    }

    float acc[4][4][4];
#pragma unroll
    for (int mt = 0; mt < 4; mt++)
#pragma unroll
        for (int nt = 0; nt < 4; nt++)
#pragma unroll
            for (int q = 0; q < 4; q++) acc[mt][nt][q] = 0.f;

    for (int ck = 0; ck < NCH; ck++) {
        cpa_wait0();
        __syncthreads();

        if (ck < NCH - 1) {               // prefetch ck+1 into the other buffer
            const __half* src = g_Wh + (ck + 1) * 8192;
            uint32_t dbase = wb_u32 + (uint32_t)(((ck + 1) & 1) * WBYTES);
#pragma unroll
            for (int r = 0; r < 2; r++) {
                int idx = tid + r * 512;
                int o = idx >> 2, c4 = idx & 3;
                cpa16(dbase + (uint32_t)(o * 96 + c4 * 16), src + o * 32 + c4 * 8);
            }
            cpa_commit();
        }

        // ---- compute chunk ck (K=32 -> 2 ksteps of 16) ----
        const __half* wcur = wb + (ck & 1) * (WBYTES / 2);
        int hk = (ck & 7) * 32;
#pragma unroll
        for (int ks = 0; ks < 2; ks++) {
            uint32_t a[4][4];
#pragma unroll
            for (int mt = 0; mt < 4; mt++) {
                const __half* ap = h + (mrow + mt * 16 + (lane >> 2)) * HSTR2
                                     + hk + ks * 16 + 4 * (lane & 3);
                uint2 lo = *(const uint2*)ap;               // k 2t..2t+1, 2t+8..2t+9
                uint2 hi = *(const uint2*)(ap + 8 * HSTR2); // row +8
                a[mt][0] = lo.x; a[mt][2] = lo.y;
                a[mt][1] = hi.x; a[mt][3] = hi.y;
            }
#pragma unroll
            for (int nt = 0; nt < 4; nt++) {
                const __half* wp = wcur + (ncol + nt * 8 + (lane >> 2)) * WS2
                                        + ks * 16 + 4 * (lane & 3);
                uint2 bv = *(const uint2*)wp;
                uint32_t bfr[2] = {bv.x, bv.y};
#pragma unroll
                for (int mt = 0; mt < 4; mt++) mma16(acc[mt][nt], a[mt], bfr);
            }
        }

        if (ck == 7) {
            // layer boundary: all layer-1 h reads done, overwrite with h2
            __syncthreads();
#pragma unroll
            for (int mt = 0; mt < 4; mt++) {
                int r = mrow + mt * 16 + (lane >> 2);
#pragma unroll
                for (int nt = 0; nt < 4; nt++) {
                    int c0 = ncol + nt * 8 + 2 * (lane & 3);
                    int p  = pg16(c0);          // even -> p, p+1 adjacent
                    __half2 v01 = __floats2half2_rn(fmaxf(acc[mt][nt][0], 0.f),
                                                    fmaxf(acc[mt][nt][1], 0.f));
                    __half2 v23 = __floats2half2_rn(fmaxf(acc[mt][nt][2], 0.f),
                                                    fmaxf(acc[mt][nt][3], 0.f));
                    *(__half2*)(h + r * HSTR2 + p)       = v01;
                    *(__half2*)(h + (r + 8) * HSTR2 + p) = v23;
#pragma unroll
                    for (int q = 0; q < 4; q++) acc[mt][nt][q] = 0.f;
                }
            }
            // next iteration's top __syncthreads orders writes before reads
        }
    }

    // ---- epilogue: relu + deterministic sum over 128 rows ----
    __syncthreads();                 // weight-buffer reads done; reuse as scratch
    float* red = (float*)wb;         // [2][256]
#pragma unroll
    for (int nt = 0; nt < 4; nt++) {
        float ev = 0.f, od = 0.f;
#pragma unroll
        for (int mt = 0; mt < 4; mt++) {
            ev += fmaxf(acc[mt][nt][0], 0.f) + fmaxf(acc[mt][nt][2], 0.f);
            od += fmaxf(acc[mt][nt][1], 0.f) + fmaxf(acc[mt][nt][3], 0.f);
        }
#pragma unroll
        for (int o = 4; o <= 16; o <<= 1) {
            ev += __shfl_xor_sync(0xffffffffu, ev, o);
            od += __shfl_xor_sync(0xffffffffu, od, o);
        }
        if (lane < 4) {
            red[wy * C2 + ncol + nt * 8 + 2 * lane]     = ev;
            red[wy * C2 + ncol + nt * 8 + 2 * lane + 1] = od;
        }
    }
    __syncthreads();
    if (tid < C2)
        g_part[(b * NI + i) * C2 + tid] = red[tid] + red[C2 + tid];
}

// ---------------------------------------------------------------------------
__global__ void k_fin(float* __restrict__ out)
{
    int idx = blockIdx.x * 256 + threadIdx.x;
    int c = idx & 255, bn = idx >> 8;
    int b = bn >> 4, n1 = bn & 15;
    float sum = 0.f;
#pragma unroll
    for (int k1 = 0; k1 < 8; k1++)
        sum += g_part[(b * NI + n1 * 8 + k1) * C2 + c];
    out[idx] = sum * (1.0f / 1024.0f);
}

// ---------------------------------------------------------------------------
extern "C" void kernel_launch(void* const* d_in, const int* in_sizes, int n_in,
                              void* d_out, int out_size)
{
    const float* enc = (const float*)d_in[0];
    const float* W1  = (const float*)d_in[1];
    const float* W2  = (const float*)d_in[2];
    const float* W3  = (const float*)d_in[3];
    float* out       = (float*)d_out;

    const int smem_bytes = 128 * HSTR2 * 2 + 2 * WBYTES;   // 69632 + 49152 = 118784
    cudaFuncSetAttribute(k_main, cudaFuncAttributeMaxDynamicSharedMemorySize, smem_bytes);

    k_round<<<131072 / 256, 256>>>(W2, W3);
    k_ab   <<<BB * NI / 8, 256>>>(enc, W1);
    k_main <<<BB * NI, 512, smem_bytes>>>();
    k_fin  <<<(BB * NN * C2) / 256, 256>>>(out);
}

// round 6
// speedup vs baseline: 16.1539x; 1.0828x over previous
#include <cuda_runtime.h>
#include <cuda_fp16.h>
#include <cstdint>

// Problem constants
#define BB 16
#define NN 16
#define HH 128
#define C2 256
#define NI 128

#define NCHUNK 8             // 4 K-chunks (of 64) x 2 layers
#define WBUF   32768         // one weight buffer: 256 rows x 128 B (no pad, XOR swizzle)
#define HBUF   32768         // h tile: 64 rows x 512 B (no pad, XOR swizzle)

// Scratch (device globals: allocation-free contract)
__device__ float g_A   [BB * NI * C2];
__device__ float g_Bvt [BB * C2 * NI];
__device__ float g_part[BB * NI * 2 * C2];
__device__ __align__(16) __half g_Wh[NCHUNK * 256 * 64];  // fp16, chunk-major, k-permuted

__device__ __forceinline__ uint32_t smem_u32(const void* p) {
    return (uint32_t)__cvta_generic_to_shared(p);
}
__device__ __forceinline__ void cpa16(uint32_t dst, const void* src) {
    asm volatile("cp.async.cg.shared.global [%0], [%1], 16;" :: "r"(dst), "l"(src));
}
__device__ __forceinline__ void cpa_commit() { asm volatile("cp.async.commit_group;"); }
__device__ __forceinline__ void cpa_wait0()  { asm volatile("cp.async.wait_group 0;"); }

__device__ __forceinline__ void mma16(float* c, const uint32_t* a, const uint32_t* b) {
    asm volatile(
        "mma.sync.aligned.m16n8k16.row.col.f32.f16.f16.f32 "
        "{%0,%1,%2,%3}, {%4,%5,%6,%7}, {%8,%9}, {%0,%1,%2,%3};"
        : "+f"(c[0]), "+f"(c[1]), "+f"(c[2]), "+f"(c[3])
        : "r"(a[0]), "r"(a[1]), "r"(a[2]), "r"(a[3]), "r"(b[0]), "r"(b[1]));
}

// k-permutation within each 16-group: (2t,2t+1,2t+8,2t+9) -> contiguous (LDS.64 frags)
__device__ __forceinline__ int pg16(int c) {
    return (c & ~15) | ((c & 6) << 1) | ((c & 8) >> 2) | (c & 1);
}

// ---------------------------------------------------------------------------
// k_round: W2|W3 -> fp16(rn), layout [8 chunks][256 o][64 k, 16-group-permuted]
// ---------------------------------------------------------------------------
__global__ void k_round(const float* __restrict__ W2, const float* __restrict__ W3)
{
    int idx = blockIdx.x * 256 + threadIdx.x;   // 131072
    int L = idx >> 16, rem = idx & 65535;
    int o = rem >> 8, k = rem & 255;
    float v = (L ? W3 : W2)[o * C2 + k];
    int ck = (L << 2) | (k >> 6);
    int k6 = k & 63;
    int k4 = k6 & 15;
    int pk = (k6 & 48) | ((k4 & 6) << 1) | ((k4 & 8) >> 2) | (k4 & 1);
    g_Wh[ck * 16384 + o * 64 + pk] = __float2half_rn(v);
}

// ---------------------------------------------------------------------------
// k_ab: layer-1 half projections (16 vectors/block, 128 blocks)
// ---------------------------------------------------------------------------
__global__ __launch_bounds__(256) void k_ab(const float* __restrict__ enc,
                                            const float* __restrict__ W1)
{
    __shared__ float e_s[16 * HH];
    __shared__ float w_s[C2 * 33];
    int tid = threadIdx.x;
    int vb  = blockIdx.x * 16;

#pragma unroll
    for (int r = 0; r < 2; r++)
        ((float4*)e_s)[tid + r * 256] = ((const float4*)(enc + vb * HH))[tid + r * 256];

    float acc[2][16];
#pragma unroll
    for (int hf = 0; hf < 2; hf++)
#pragma unroll
        for (int v = 0; v < 16; v++) acc[hf][v] = 0.f;

    for (int kt = 0; kt < C2; kt += 32) {
        __syncthreads();
#pragma unroll
        for (int r = 0; r < 8; r++) {
            int idx = tid + r * 256;
            int o = idx >> 3, c4 = idx & 7;
            float4 w4 = *(const float4*)(W1 + o * C2 + kt + c4 * 4);
            w_s[o * 33 + c4 * 4 + 0] = w4.x;
            w_s[o * 33 + c4 * 4 + 1] = w4.y;
            w_s[o * 33 + c4 * 4 + 2] = w4.z;
            w_s[o * 33 + c4 * 4 + 3] = w4.w;
        }
        __syncthreads();
        int hf = kt >> 7, kb = kt & 127;
#pragma unroll 8
        for (int kk = 0; kk < 32; kk++) {
            float wv = w_s[tid * 33 + kk];
#pragma unroll
            for (int v = 0; v < 16; v++)
                acc[hf][v] = fmaf(wv, e_s[v * HH + kb + kk], acc[hf][v]);
        }
    }
    int b = vb >> 7, i0 = vb & 127;
#pragma unroll
    for (int v = 0; v < 16; v++) {
        g_A  [(vb + v) * C2 + tid]          = acc[0][v];
        g_Bvt[(b * C2 + tid) * NI + i0 + v] = acc[1][v];
    }
}

// ---------------------------------------------------------------------------
// k_main: fused 2-layer GEMM, fp16 m16n8k16, 2 CTAs/SM.
// CTA = (b, i, jhalf): M=64 rows x 256 cols, K=256, two layers.
// 256 threads, 8 warps: wy in {0,1} (32 rows), wx in {0..3} (64 cols).
// h: 64 rows x 512B, phys = row*512 + (inner ^ ((row&3)<<5))   [conflict-free]
// W: 256 rows x 128B, phys = o*128  + (inner ^ ((o&3)<<5))     [conflict-free]
// smem = 32K (h) + 2*32K (W ring) = 96K -> 2 CTAs/SM.
// ---------------------------------------------------------------------------
__global__ __launch_bounds__(256, 2) void k_main()
{
    extern __shared__ char smem[];
    char* hb = smem;                       // h tile, 32 KB
    char* wbase = smem + HBUF;             // 2 weight buffers, 64 KB
    uint32_t w_u32 = smem_u32(wbase);

    int tid  = threadIdx.x;
    int lane = tid & 31;
    int wid  = tid >> 3 >> 2;              // wid = tid>>5
    int wy   = wid & 1;
    int wx   = wid >> 1;
    int mrow = wy * 32;
    int ncol = wx * 64;

    int blk = blockIdx.x;
    int b   = blk >> 8;
    int rem = blk & 255;
    int i   = rem >> 1;
    int jh  = rem & 1;
    int j0  = jh * 64;

    // ---- prefetch chunk 0 (2048 x 16B / 256 threads = 8 each) ----
#pragma unroll
    for (int r = 0; r < 8; r++) {
        int idx = tid + r * 256;
        int o = idx >> 3, c4 = idx & 7;
        uint32_t inner = (uint32_t)((c4 * 16) ^ ((o & 3) << 5));
        cpa16(w_u32 + (uint32_t)o * 128 + inner, g_Wh + o * 64 + c4 * 8);
    }
    cpa_commit();

    // ---- build h1 while chunk 0 flies ----
    {
        int p   = tid & 127;               // half2 column pair: cols 2p, 2p+1
        int rg  = tid >> 7;                // row group: rows rg*32 .. rg*32+31
        int c0  = 2 * p;
        float a0 = g_A[(b * NI + i) * C2 + c0];
        float a1 = g_A[(b * NI + i) * C2 + c0 + 1];
        const float* bp0 = g_Bvt + (b * C2 + c0)     * NI + j0 + rg * 32;
        const float* bp1 = g_Bvt + (b * C2 + c0 + 1) * NI + j0 + rg * 32;
        int pcb = pg16(c0) * 2;            // even pair -> adjacent bytes, 4B aligned
#pragma unroll
        for (int r4 = 0; r4 < 32; r4 += 4) {
            float4 v0 = *(const float4*)(bp0 + r4);
            float4 v1 = *(const float4*)(bp1 + r4);
            int row = rg * 32 + r4;
#pragma unroll
            for (int q = 0; q < 4; q++) {
                float e0 = (q == 0 ? v0.x : q == 1 ? v0.y : q == 2 ? v0.z : v0.w);
                float e1 = (q == 0 ? v1.x : q == 1 ? v1.y : q == 2 ? v1.z : v1.w);
                __half2 hv = __floats2half2_rn(fmaxf(e0 + a0, 0.f), fmaxf(e1 + a1, 0.f));
                int rr = row + q;
                *(__half2*)(hb + rr * 512 + (pcb ^ ((rr & 3) << 5))) = hv;
            }
        }
    }

    float acc[2][8][4];
#pragma unroll
    for (int mt = 0; mt < 2; mt++)
#pragma unroll
        for (int nt = 0; nt < 8; nt++)
#pragma unroll
            for (int q = 0; q < 4; q++) acc[mt][nt][q] = 0.f;

    for (int ck = 0; ck < NCHUNK; ck++) {
        cpa_wait0();
        __syncthreads();

        if (ck < NCHUNK - 1) {             // prefetch ck+1 into the other buffer
            const __half* src = g_Wh + (ck + 1) * 16384;
            uint32_t dbase = w_u32 + (uint32_t)(((ck + 1) & 1) * WBUF);
#pragma unroll
            for (int r = 0; r < 8; r++) {
                int idx = tid + r * 256;
                int o = idx >> 3, c4 = idx & 7;
                uint32_t inner = (uint32_t)((c4 * 16) ^ ((o & 3) << 5));
                cpa16(dbase + (uint32_t)o * 128 + inner, src + o * 64 + c4 * 8);
            }
            cpa_commit();
        }

        // ---- compute chunk ck (K=64 -> 4 ksteps of 16) ----
        char* wc  = wbase + (ck & 1) * WBUF;
        int   ckb = (ck & 3) * 128;        // chunk byte offset within h row
#pragma unroll
        for (int ks = 0; ks < 4; ks++) {
            uint32_t a[2][4];
#pragma unroll
            for (int mt = 0; mt < 2; mt++) {
                int r0 = mrow + mt * 16 + (lane >> 2);
                uint32_t inner = (uint32_t)((ckb + ks * 32 + (lane & 3) * 8));
                uint2 lo = *(const uint2*)(hb + r0 * 512 + (inner ^ ((r0 & 3) << 5)));
                int r8 = r0 + 8;
                uint2 hi = *(const uint2*)(hb + r8 * 512 + (inner ^ ((r8 & 3) << 5)));
                a[mt][0] = lo.x; a[mt][2] = lo.y;
                a[mt][1] = hi.x; a[mt][3] = hi.y;
            }
#pragma unroll
            for (int nt = 0; nt < 8; nt++) {
                int o = ncol + nt * 8 + (lane >> 2);
                uint32_t inner = (uint32_t)((ks * 32 + (lane & 3) * 8) ^ ((o & 3) << 5));
                uint2 bv = *(const uint2*)(wc + o * 128 + inner);
                uint32_t bfr[2] = {bv.x, bv.y};
                mma16(acc[0][nt], a[0], bfr);
                mma16(acc[1][nt], a[1], bfr);
            }
        }

        if (ck == 3) {
            // layer boundary: overwrite h with h2 (same permuted+swizzled layout)
            __syncthreads();
#pragma unroll
            for (int mt = 0; mt < 2; mt++) {
                int r = mrow + mt * 16 + (lane >> 2);
#pragma unroll
                for (int nt = 0; nt < 8; nt++) {
                    int c0 = ncol + nt * 8 + 2 * (lane & 3);
                    int pcb = pg16(c0) * 2;
                    __half2 v01 = __floats2half2_rn(fmaxf(acc[mt][nt][0], 0.f),
                                                    fmaxf(acc[mt][nt][1], 0.f));
                    __half2 v23 = __floats2half2_rn(fmaxf(acc[mt][nt][2], 0.f),
                                                    fmaxf(acc[mt][nt][3], 0.f));
                    int r8 = r + 8;
                    *(__half2*)(hb + r * 512 + (pcb ^ ((r & 3) << 5)))   = v01;
                    *(__half2*)(hb + r8 * 512 + (pcb ^ ((r8 & 3) << 5))) = v23;
#pragma unroll
                    for (int q = 0; q < 4; q++) acc[mt][nt][q] = 0.f;
                }
            }
            // next iteration's top __syncthreads orders writes before reads
        }
    }

    // ---- epilogue: relu + deterministic sum over the CTA's 64 rows ----
    __syncthreads();                       // weight-ring reads done; reuse as scratch
    float* red = (float*)wbase;            // [2][256]
#pragma unroll
    for (int nt = 0; nt < 8; nt++) {
        float ev = 0.f, od = 0.f;
#pragma unroll
        for (int mt = 0; mt < 2; mt++) {
            ev += fmaxf(acc[mt][nt][0], 0.f) + fmaxf(acc[mt][nt][2], 0.f);
            od += fmaxf(acc[mt][nt][1], 0.f) + fmaxf(acc[mt][nt][3], 0.f);
        }
#pragma unroll
        for (int o = 4; o <= 16; o <<= 1) {
            ev += __shfl_xor_sync(0xffffffffu, ev, o);
            od += __shfl_xor_sync(0xffffffffu, od, o);
        }
        if (lane < 4) {
            red[wy * C2 + ncol + nt * 8 + 2 * lane]     = ev;
            red[wy * C2 + ncol + nt * 8 + 2 * lane + 1] = od;
        }
    }
    __syncthreads();
    g_part[((b * NI + i) * 2 + jh) * C2 + tid] = red[tid] + red[C2 + tid];
}

// ---------------------------------------------------------------------------
__global__ void k_fin(float* __restrict__ out)
{
    int idx = blockIdx.x * 256 + threadIdx.x;
    int c = idx & 255, bn = idx >> 8;
    int b = bn >> 4, n1 = bn & 15;
    float sum = 0.f;
#pragma unroll
    for (int k1 = 0; k1 < 8; k1++)
#pragma unroll
        for (int jhv = 0; jhv < 2; jhv++)
            sum += g_part[((b * NI + n1 * 8 + k1) * 2 + jhv) * C2 + c];
    out[idx] = sum * (1.0f / 1024.0f);
}

// ---------------------------------------------------------------------------
extern "C" void kernel_launch(void* const* d_in, const int* in_sizes, int n_in,
                              void* d_out, int out_size)
{
    const float* enc = (const float*)d_in[0];
    const float* W1  = (const float*)d_in[1];
    const float* W2  = (const float*)d_in[2];
    const float* W3  = (const float*)d_in[3];
    float* out       = (float*)d_out;

    const int smem_bytes = HBUF + 2 * WBUF;   // 98304
    cudaFuncSetAttribute(k_main, cudaFuncAttributeMaxDynamicSharedMemorySize, smem_bytes);

    k_round<<<131072 / 256, 256>>>(W2, W3);
    k_ab   <<<BB * NI / 16, 256>>>(enc, W1);
    k_main <<<BB * NI * 2, 256, smem_bytes>>>();
    k_fin  <<<(BB * NN * C2) / 256, 256>>>(out);
}